// round 12
// baseline (speedup 1.0000x reference)
#include <cuda_runtime.h>
#include <cuda_fp16.h>
#include <stdint.h>

// ---------------------------------------------------------------------------
// Problem constants
// ---------------------------------------------------------------------------
constexpr int NB = 32;
constexpr int NT = 1024;
constexpr int ND = 2048;
constexpr int NU = 1024;

// GEMM tiling: C[32768,1024] = A[32768,2048] * B[2048,1024] (B = W1)
constexpr int CTA_M = 128;
constexpr int CTA_N = 256;
constexpr int KC    = 64;           // k-chunk (64 fp16 = 128B row -> SW128)
constexpr int NKT   = ND / KC;      // 32
constexpr int NSLAB = NU / CTA_N;   // 4 partial-score slabs
constexpr int NSTG  = 4;            // cp.async pipeline stages

constexpr int STAGE_BYTES = CTA_M * KC * 2 + CTA_N * KC * 2;  // 16K + 32K = 48K
constexpr int SMEM_DYN    = 1024 + NSTG * STAGE_BYTES;        // 197632

#define SW128(o) ((o) ^ (((o) >> 3) & 0x70))

// ---------------------------------------------------------------------------
// Device scratch (__device__ globals: allocation-free rule)
// ---------------------------------------------------------------------------
__device__ __align__(256) __half g_valh[(size_t)NB * NT * ND];  // values in fp16
__device__ __align__(256) __half g_w1h[(size_t)NU * ND];        // W1^T fp16 [U][D]
__device__ float g_qproj[NB * NU];                              // q@W2 + b1 + b2
__device__ float g_pscore[NSLAB * NB * NT];                     // partial scores

// ---------------------------------------------------------------------------
// PTX helpers (baseline sm_80 features only: safe for compute_103 target)
// ---------------------------------------------------------------------------
__device__ __forceinline__ uint32_t sptr(const void* p) {
    return (uint32_t)__cvta_generic_to_shared(p);
}

__device__ __forceinline__ void cpasync16(uint32_t dst, const void* src) {
    asm volatile("cp.async.cg.shared.global [%0], [%1], 16;" :: "r"(dst), "l"(src));
}
#define CP_COMMIT() asm volatile("cp.async.commit_group;" ::: "memory")
#define CP_WAIT2()  asm volatile("cp.async.wait_group 2;" ::: "memory")

__device__ __forceinline__ void ldsm4(uint32_t* r, uint32_t addr) {
    asm volatile("ldmatrix.sync.aligned.m8n8.x4.shared.b16 {%0,%1,%2,%3}, [%4];"
                 : "=r"(r[0]), "=r"(r[1]), "=r"(r[2]), "=r"(r[3]) : "r"(addr));
}

__device__ __forceinline__ void mma16816(float* d, const uint32_t* a,
                                         const uint32_t* b) {
    asm volatile(
        "mma.sync.aligned.m16n8k16.row.col.f32.f16.f16.f32 "
        "{%0,%1,%2,%3}, {%4,%5,%6,%7}, {%8,%9}, {%0,%1,%2,%3};"
        : "+f"(d[0]), "+f"(d[1]), "+f"(d[2]), "+f"(d[3])
        : "r"(a[0]), "r"(a[1]), "r"(a[2]), "r"(a[3]), "r"(b[0]), "r"(b[1]));
}

// fast accurate tanh: 1 - 2/(exp(2x)+1); saturates correctly at +-inf
__device__ __forceinline__ float fast_tanh(float x) {
    float e = __expf(2.0f * x);
    return 1.0f - __fdividef(2.0f, e + 1.0f);
}

__device__ __forceinline__ uint32_t pack_h2(float a, float b) {
    __half2 h = __floats2half2_rn(a, b);
    return *(uint32_t*)&h;
}

// ---------------------------------------------------------------------------
// Kernel 1 (fused prep): qproj blocks | W1 transpose blocks | values->fp16
// values convert: 16 floats per thread (MLP=4 LDG.128, 2x STG.128)
// ---------------------------------------------------------------------------
constexpr int QP_BLOCKS = NB * (NU / 256);            // 128
constexpr int PW_BLOCKS = (NU / 32) * (ND / 32);      // 2048
constexpr int PV_BLOCKS = (int)(((size_t)NB * NT * ND) / (256 * 16));  // 16384
constexpr int PREP_BLOCKS = QP_BLOCKS + PW_BLOCKS + PV_BLOCKS;

__global__ void __launch_bounds__(256) fused_prep_kernel(
    const float* __restrict__ values, const float* __restrict__ W1,
    const float* __restrict__ query,  const float* __restrict__ W2,
    const float* __restrict__ b1,     const float* __restrict__ b2) {
    int bi = blockIdx.x;
    int tid = threadIdx.x;

    if (bi < QP_BLOCKS) {
        // qproj[b][u] = query[b]@W2[:,u] + b1[u] + b2[u]   (8-wide MLP)
        int b = bi >> 2;
        int u = (bi & 3) * 256 + tid;
        const float* q = query + (size_t)b * ND;
        float a0 = 0.f, a1 = 0.f, a2 = 0.f, a3 = 0.f;
        float a4 = 0.f, a5 = 0.f, a6 = 0.f, a7 = 0.f;
        #pragma unroll 2
        for (int d = 0; d < ND; d += 8) {
            a0 = fmaf(q[d + 0], W2[(size_t)(d + 0) * NU + u], a0);
            a1 = fmaf(q[d + 1], W2[(size_t)(d + 1) * NU + u], a1);
            a2 = fmaf(q[d + 2], W2[(size_t)(d + 2) * NU + u], a2);
            a3 = fmaf(q[d + 3], W2[(size_t)(d + 3) * NU + u], a3);
            a4 = fmaf(q[d + 4], W2[(size_t)(d + 4) * NU + u], a4);
            a5 = fmaf(q[d + 5], W2[(size_t)(d + 5) * NU + u], a5);
            a6 = fmaf(q[d + 6], W2[(size_t)(d + 6) * NU + u], a6);
            a7 = fmaf(q[d + 7], W2[(size_t)(d + 7) * NU + u], a7);
        }
        g_qproj[b * NU + u] = b1[u] + b2[u] +
            (((a0 + a1) + (a2 + a3)) + ((a4 + a5) + (a6 + a7)));
        return;
    }
    bi -= QP_BLOCKS;
    if (bi < PW_BLOCKS) {
        // W1 [D][U] fp32 -> W1^T [U][D] fp16, 32x32 tiles
        __shared__ __half tile[32][33];
        int u0 = (bi & 31) * 32;          // NU/32 = 32
        int d0 = (bi >> 5) * 32;
        int c = tid & 31;
        int r0 = tid >> 5;
        #pragma unroll
        for (int rr = 0; rr < 4; rr++) {
            int r = r0 + rr * 8;
            tile[r][c] = __float2half(W1[(size_t)(d0 + r) * NU + u0 + c]);
        }
        __syncthreads();
        #pragma unroll
        for (int rr = 0; rr < 4; rr++) {
            int r = r0 + rr * 8;
            g_w1h[(size_t)(u0 + r) * ND + d0 + c] = tile[c][r];
        }
        return;
    }
    bi -= PW_BLOCKS;
    // values fp32 -> fp16: 16 consecutive floats per thread
    size_t base = ((size_t)bi * 256 + tid) * 16;
    const float4* src = (const float4*)(values + base);
    float4 x0 = src[0];
    float4 x1 = src[1];
    float4 x2 = src[2];
    float4 x3 = src[3];
    uint4 o0, o1;
    o0.x = pack_h2(x0.x, x0.y); o0.y = pack_h2(x0.z, x0.w);
    o0.z = pack_h2(x1.x, x1.y); o0.w = pack_h2(x1.z, x1.w);
    o1.x = pack_h2(x2.x, x2.y); o1.y = pack_h2(x2.z, x2.w);
    o1.z = pack_h2(x3.x, x3.y); o1.w = pack_h2(x3.z, x3.w);
    uint4* dst = (uint4*)(g_valh + base);
    dst[0] = o0;
    dst[1] = o1;
}

// ---------------------------------------------------------------------------
// Kernel 2: fused fp16 GEMM (mma.sync, 4-stage cp.async) + tanh + dot(V)
// grid (NSLAB, 256 m-tiles), 256 threads, 1 CTA/SM
// ---------------------------------------------------------------------------
__global__ void __launch_bounds__(256, 1)
gemm_score_kernel(const float* __restrict__ Vv) {
    extern __shared__ char dynsmem[];
    __shared__ float s_qp[CTA_N];
    __shared__ float s_V[CTA_N];
    __shared__ float s_red[CTA_M][4];

    const int tid  = threadIdx.x;
    const int wid  = tid >> 5;
    const int lane = tid & 31;
    const int uslab = blockIdx.x;
    const int mtile = blockIdx.y;
    const size_t arow0 = (size_t)mtile * CTA_M;   // global row = b*NT + t0
    const int u0 = uslab * CTA_N;
    const int mwarp = wid & 1;        // 2 warps along M
    const int nwarp = wid >> 1;       // 4 warps along N

    // 1024B-aligned SMEM base (SW128 swizzle requires it)
    const uint32_t sb = sptr(dynsmem);
    const uint32_t tb = (sb + 1023u) & ~1023u;

    for (int i = tid; i < CTA_N; i += 256) {
        s_qp[i] = g_qproj[(arow0 >> 10) * NU + u0 + i];   // b = arow0/1024
        s_V[i]  = Vv[u0 + i];
    }

    const __half* asrc0 = g_valh + arow0 * ND;
    const __half* bsrc0 = g_w1h + (size_t)u0 * ND;

    // ---- stage loader: A 128x64 fp16 + B 256x64 fp16, SW128 swizzled ----
    auto load_stage = [&](int kt, int st) {
        uint32_t ab = tb + st * STAGE_BYTES;
        uint32_t bb = ab + CTA_M * KC * 2;
        const __half* asrc = asrc0 + (size_t)kt * KC;
        #pragma unroll
        for (int i = 0; i < 4; i++) {           // 1024 chunks of 16B
            int c = tid + i * 256;
            int r = c >> 3, k8 = c & 7;
            cpasync16(ab + SW128((uint32_t)(r * 128 + k8 * 16)),
                      asrc + (size_t)r * ND + k8 * 8);
        }
        const __half* bsrc = bsrc0 + (size_t)kt * KC;
        #pragma unroll
        for (int i = 0; i < 8; i++) {           // 2048 chunks of 16B
            int c = tid + i * 256;
            int r = c >> 3, k8 = c & 7;
            cpasync16(bb + SW128((uint32_t)(r * 128 + k8 * 16)),
                      bsrc + (size_t)r * ND + k8 * 8);
        }
        CP_COMMIT();
    };

    float acc[4][8][4];
    #pragma unroll
    for (int mt = 0; mt < 4; mt++)
        #pragma unroll
        for (int nt = 0; nt < 8; nt++)
            #pragma unroll
            for (int i = 0; i < 4; i++) acc[mt][nt][i] = 0.f;

    load_stage(0, 0);
    load_stage(1, 1);
    load_stage(2, 2);

    for (int kt = 0; kt < NKT; kt++) {
        CP_WAIT2();              // oldest (stage kt) complete for this thread
        __syncthreads();         // whole tile visible; stage (kt+3)%4 drained
        if (kt + 3 < NKT) load_stage(kt + 3, (kt + 3) & 3);
        else              CP_COMMIT();       // keep group accounting aligned

        uint32_t ab = tb + (kt & 3) * STAGE_BYTES;
        uint32_t bb = ab + CTA_M * KC * 2;

        #pragma unroll
        for (int ks = 0; ks < 4; ks++) {        // 4 k16-steps per chunk
            uint32_t a_r[4][4], b_r[4][4];
            #pragma unroll
            for (int mt = 0; mt < 4; mt++) {
                int r    = mwarp * 64 + mt * 16 + (lane & 15);
                int kcol = ks * 16 + ((lane >> 4) << 3);
                ldsm4(a_r[mt], ab + SW128((uint32_t)(r * 128 + kcol * 2)));
            }
            #pragma unroll
            for (int j = 0; j < 4; j++) {       // each covers 2 n-tiles (n16)
                int r    = nwarp * 64 + j * 16 + (lane & 7) + ((lane >> 4) << 3);
                int kcol = ks * 16 + ((lane >> 3) & 1) * 8;
                ldsm4(b_r[j], bb + SW128((uint32_t)(r * 128 + kcol * 2)));
            }
            #pragma unroll
            for (int mt = 0; mt < 4; mt++)
                #pragma unroll
                for (int nt = 0; nt < 8; nt++)
                    mma16816(acc[mt][nt], a_r[mt], b_r[nt >> 1] + (nt & 1) * 2);
        }
    }

    // ---- epilogue: per-row partial score = sum_u tanh(c + qp[u]) * V[u] ----
    #pragma unroll
    for (int mt = 0; mt < 4; mt++) {
        float rs0 = 0.f, rs1 = 0.f;   // rows (base) and (base+8)
        #pragma unroll
        for (int nt = 0; nt < 8; nt++) {
            int col = nwarp * 64 + nt * 8 + (lane & 3) * 2;
            rs0 += fast_tanh(acc[mt][nt][0] + s_qp[col])     * s_V[col];
            rs0 += fast_tanh(acc[mt][nt][1] + s_qp[col + 1]) * s_V[col + 1];
            rs1 += fast_tanh(acc[mt][nt][2] + s_qp[col])     * s_V[col];
            rs1 += fast_tanh(acc[mt][nt][3] + s_qp[col + 1]) * s_V[col + 1];
        }
        rs0 += __shfl_xor_sync(0xFFFFFFFF, rs0, 1);
        rs0 += __shfl_xor_sync(0xFFFFFFFF, rs0, 2);
        rs1 += __shfl_xor_sync(0xFFFFFFFF, rs1, 1);
        rs1 += __shfl_xor_sync(0xFFFFFFFF, rs1, 2);
        if ((lane & 3) == 0) {
            int row = mwarp * 64 + mt * 16 + (lane >> 2);
            s_red[row][nwarp]     = rs0;
            s_red[row + 8][nwarp] = rs1;
        }
    }
    __syncthreads();
    if (tid < CTA_M) {
        float s = s_red[tid][0] + s_red[tid][1] + s_red[tid][2] + s_red[tid][3];
        g_pscore[(size_t)uslab * NB * NT + arow0 + tid] = s;
    }
}

// ---------------------------------------------------------------------------
// Kernel 3: fused softmax + context. grid (NB, ND/512), 256 threads.
// Each block redundantly computes the (tiny) softmax for its batch, then
// does the weighted sum over fp16 values for its 512-d slice (half2/thread).
// ---------------------------------------------------------------------------
__global__ void __launch_bounds__(256) softmax_context_kernel(
    float* __restrict__ out_w, float* __restrict__ out_ctx) {
    __shared__ float sw_[NT];
    __shared__ float red[256];
    const int b = blockIdx.x;
    const int tid = threadIdx.x;

    float s[4];
    float m = -3.0e38f;
    #pragma unroll
    for (int j = 0; j < 4; j++) {
        int t = j * 256 + tid;
        float v = 0.f;
        #pragma unroll
        for (int k = 0; k < NSLAB; k++)
            v += g_pscore[k * NB * NT + b * NT + t];
        s[j] = v;
        m = fmaxf(m, v);
    }
    red[tid] = m;
    __syncthreads();
    #pragma unroll
    for (int k = 128; k > 0; k >>= 1) {
        if (tid < k) red[tid] = fmaxf(red[tid], red[tid + k]);
        __syncthreads();
    }
    float mx = red[0];
    __syncthreads();
    float sum = 0.f;
    #pragma unroll
    for (int j = 0; j < 4; j++) { s[j] = __expf(s[j] - mx); sum += s[j]; }
    red[tid] = sum;
    __syncthreads();
    #pragma unroll
    for (int k = 128; k > 0; k >>= 1) {
        if (tid < k) red[tid] += red[tid + k];
        __syncthreads();
    }
    float inv = 1.0f / red[0];
    #pragma unroll
    for (int j = 0; j < 4; j++) {
        int t = j * 256 + tid;
        float w = s[j] * inv;
        sw_[t] = w;
        if (blockIdx.y == 0) out_w[b * NT + t] = w;
    }
    __syncthreads();

    // context slice: 2 adjacent d per thread (half2), d in [y*512, +512)
    int d = blockIdx.y * 512 + tid * 2;
    const __half2* vp = (const __half2*)(g_valh + (size_t)b * NT * ND + d);
    constexpr int S2 = ND / 2;   // half2 stride per t
    float c0 = 0.f, c1 = 0.f, c2 = 0.f, c3 = 0.f;   // interleaved accum x2 cols
    #pragma unroll 2
    for (int t = 0; t < NT; t += 2) {
        float2 v0 = __half22float2(vp[(size_t)(t + 0) * S2]);
        float2 v1 = __half22float2(vp[(size_t)(t + 1) * S2]);
        c0 = fmaf(sw_[t + 0], v0.x, c0);
        c1 = fmaf(sw_[t + 0], v0.y, c1);
        c2 = fmaf(sw_[t + 1], v1.x, c2);
        c3 = fmaf(sw_[t + 1], v1.y, c3);
    }
    float2 outv = make_float2(c0 + c2, c1 + c3);
    *(float2*)(out_ctx + b * ND + d) = outv;
}

// ---------------------------------------------------------------------------
// Launch
// ---------------------------------------------------------------------------
extern "C" void kernel_launch(void* const* d_in, const int* in_sizes, int n_in,
                              void* d_out, int out_size) {
    (void)in_sizes; (void)n_in; (void)out_size;
    const float* query  = (const float*)d_in[0];
    const float* values = (const float*)d_in[1];
    const float* W1     = (const float*)d_in[2];
    const float* b1     = (const float*)d_in[3];
    const float* W2     = (const float*)d_in[4];
    const float* b2     = (const float*)d_in[5];
    const float* Vv     = (const float*)d_in[6];
    // d_in[7] = bv: constant pre-softmax shift -> cancels under softmax.

    float* out     = (float*)d_out;
    float* out_ctx = out;              // context_vector (B, D)
    float* out_w   = out + NB * ND;    // attention_weights (B, T, 1)

    cudaFuncSetAttribute(gemm_score_kernel,
                         cudaFuncAttributeMaxDynamicSharedMemorySize, SMEM_DYN);

    fused_prep_kernel<<<PREP_BLOCKS, 256>>>(values, W1, query, W2, b1, b2);
    gemm_score_kernel<<<dim3(NSLAB, (NB * NT) / CTA_M), 256, SMEM_DYN>>>(Vv);
    softmax_context_kernel<<<dim3(NB, ND / 512), 256>>>(out_w, out_ctx);
}

// round 14
// speedup vs baseline: 1.5561x; 1.5561x over previous
#include <cuda_runtime.h>
#include <cuda_fp16.h>
#include <stdint.h>

// ---------------------------------------------------------------------------
// Problem constants
// ---------------------------------------------------------------------------
constexpr int NB = 32;
constexpr int NT = 1024;
constexpr int ND = 2048;
constexpr int NU = 1024;

// GEMM tiling: C[32768,1024] = A[32768,2048] * B[2048,1024] (B = W1)
constexpr int CTA_M = 128;
constexpr int CTA_N = 256;
constexpr int KC    = 64;           // k-chunk (64 fp16 = 128B row -> SW128)
constexpr int NKT   = ND / KC;      // 32
constexpr int NSLAB = NU / CTA_N;   // 4 partial-score slabs
constexpr int NSTG  = 4;            // cp.async pipeline stages
constexpr int NQCH  = 4;            // qproj d-split chunks

constexpr int STAGE_BYTES = CTA_M * KC * 2 + CTA_N * KC * 2;  // 16K + 32K = 48K
constexpr int SMEM_DYN    = 1024 + NSTG * STAGE_BYTES;        // 197632

#define SW128(o) ((o) ^ (((o) >> 3) & 0x70))

// ---------------------------------------------------------------------------
// Device scratch (__device__ globals: allocation-free rule)
// ---------------------------------------------------------------------------
__device__ __align__(256) __half g_valh[(size_t)NB * NT * ND];  // values in fp16
__device__ __align__(256) __half g_w1h[(size_t)NU * ND];        // W1^T fp16 [U][D]
__device__ float g_qproj[NQCH * NB * NU];                       // partial qproj
__device__ float g_pscore[NSLAB * NB * NT];                     // partial scores

// ---------------------------------------------------------------------------
// PTX helpers (baseline sm_80 features only: safe for compute_103 target)
// ---------------------------------------------------------------------------
__device__ __forceinline__ uint32_t sptr(const void* p) {
    return (uint32_t)__cvta_generic_to_shared(p);
}

__device__ __forceinline__ void cpasync16(uint32_t dst, const void* src) {
    asm volatile("cp.async.cg.shared.global [%0], [%1], 16;" :: "r"(dst), "l"(src));
}
#define CP_COMMIT() asm volatile("cp.async.commit_group;" ::: "memory")
#define CP_WAIT2()  asm volatile("cp.async.wait_group 2;" ::: "memory")

__device__ __forceinline__ void ldsm4(uint32_t* r, uint32_t addr) {
    asm volatile("ldmatrix.sync.aligned.m8n8.x4.shared.b16 {%0,%1,%2,%3}, [%4];"
                 : "=r"(r[0]), "=r"(r[1]), "=r"(r[2]), "=r"(r[3]) : "r"(addr));
}

__device__ __forceinline__ void mma16816(float* d, const uint32_t* a,
                                         const uint32_t* b) {
    asm volatile(
        "mma.sync.aligned.m16n8k16.row.col.f32.f16.f16.f32 "
        "{%0,%1,%2,%3}, {%4,%5,%6,%7}, {%8,%9}, {%0,%1,%2,%3};"
        : "+f"(d[0]), "+f"(d[1]), "+f"(d[2]), "+f"(d[3])
        : "r"(a[0]), "r"(a[1]), "r"(a[2]), "r"(a[3]), "r"(b[0]), "r"(b[1]));
}

// fast accurate tanh: 1 - 2/(exp(2x)+1); saturates correctly at +-inf
__device__ __forceinline__ float fast_tanh(float x) {
    float e = __expf(2.0f * x);
    return 1.0f - __fdividef(2.0f, e + 1.0f);
}

__device__ __forceinline__ uint32_t pack_h2(float a, float b) {
    __half2 h = __floats2half2_rn(a, b);
    return *(uint32_t*)&h;
}

// ---------------------------------------------------------------------------
// Kernel 1 (fused prep): qproj(d-split) | W1 transpose | values->fp16
// ---------------------------------------------------------------------------
constexpr int QP_BLOCKS = NQCH * NB * (NU / 256);     // 512
constexpr int PW_BLOCKS = (NU / 32) * (ND / 32);      // 2048
// convert: 4 float4 per thread at block stride 256 (coalesced, MLP=4)
constexpr int PV_F4     = (int)(((size_t)NB * NT * ND) / 4);   // 16M float4
constexpr int PV_BLOCKS = PV_F4 / (256 * 4);                   // 16384
constexpr int PREP_BLOCKS = QP_BLOCKS + PW_BLOCKS + PV_BLOCKS;

__global__ void __launch_bounds__(256) fused_prep_kernel(
    const float* __restrict__ values, const float* __restrict__ W1,
    const float* __restrict__ query,  const float* __restrict__ W2,
    const float* __restrict__ b1,     const float* __restrict__ b2) {
    int bi = blockIdx.x;
    int tid = threadIdx.x;

    if (bi < QP_BLOCKS) {
        // partial qproj over d-chunk: chunk = bi%4, (b,u-quarter) = bi/4
        int chunk = bi & (NQCH - 1);
        int rest  = bi >> 2;
        int b = rest >> 2;
        int u = (rest & 3) * 256 + tid;
        int d0 = chunk * (ND / NQCH);                 // 512-wide chunk
        const float* q = query + (size_t)b * ND + d0;
        const float* w = W2 + (size_t)d0 * NU + u;
        float a0 = 0.f, a1 = 0.f, a2 = 0.f, a3 = 0.f;
        #pragma unroll 2
        for (int d = 0; d < ND / NQCH; d += 4) {
            a0 = fmaf(q[d + 0], w[(size_t)(d + 0) * NU], a0);
            a1 = fmaf(q[d + 1], w[(size_t)(d + 1) * NU], a1);
            a2 = fmaf(q[d + 2], w[(size_t)(d + 2) * NU], a2);
            a3 = fmaf(q[d + 3], w[(size_t)(d + 3) * NU], a3);
        }
        float r = (a0 + a1) + (a2 + a3);
        if (chunk == 0) r += b1[u] + b2[u];
        g_qproj[chunk * NB * NU + b * NU + u] = r;
        return;
    }
    bi -= QP_BLOCKS;
    if (bi < PW_BLOCKS) {
        // W1 [D][U] fp32 -> W1^T [U][D] fp16, 32x32 tiles
        __shared__ __half tile[32][33];
        int u0 = (bi & 31) * 32;          // NU/32 = 32
        int d0 = (bi >> 5) * 32;
        int c = tid & 31;
        int r0 = tid >> 5;
        #pragma unroll
        for (int rr = 0; rr < 4; rr++) {
            int r = r0 + rr * 8;
            tile[r][c] = __float2half(W1[(size_t)(d0 + r) * NU + u0 + c]);
        }
        __syncthreads();
        #pragma unroll
        for (int rr = 0; rr < 4; rr++) {
            int r = r0 + rr * 8;
            g_w1h[(size_t)(u0 + r) * ND + d0 + c] = tile[c][r];
        }
        return;
    }
    bi -= PW_BLOCKS;
    // values fp32 -> fp16: 4 float4 per thread, BLOCK-STRIDED (coalesced MLP=4)
    size_t f4base = (size_t)bi * (256 * 4) + tid;
    const float4* src = (const float4*)values;
    float4 x0 = src[f4base];
    float4 x1 = src[f4base + 256];
    float4 x2 = src[f4base + 512];
    float4 x3 = src[f4base + 768];
    uint2* dst = (uint2*)g_valh;
    dst[f4base]       = make_uint2(pack_h2(x0.x, x0.y), pack_h2(x0.z, x0.w));
    dst[f4base + 256] = make_uint2(pack_h2(x1.x, x1.y), pack_h2(x1.z, x1.w));
    dst[f4base + 512] = make_uint2(pack_h2(x2.x, x2.y), pack_h2(x2.z, x2.w));
    dst[f4base + 768] = make_uint2(pack_h2(x3.x, x3.y), pack_h2(x3.z, x3.w));
}

// ---------------------------------------------------------------------------
// Kernel 2: fused fp16 GEMM (mma.sync, 4-stage cp.async) + tanh + dot(V)
// grid (NSLAB, 256 m-tiles), 256 threads, 1 CTA/SM
// ---------------------------------------------------------------------------
__global__ void __launch_bounds__(256, 1)
gemm_score_kernel(const float* __restrict__ Vv) {
    extern __shared__ char dynsmem[];
    __shared__ float s_qp[CTA_N];
    __shared__ float s_V[CTA_N];
    __shared__ float s_red[CTA_M][4];

    const int tid  = threadIdx.x;
    const int wid  = tid >> 5;
    const int lane = tid & 31;
    const int uslab = blockIdx.x;
    const int mtile = blockIdx.y;
    const size_t arow0 = (size_t)mtile * CTA_M;   // global row = b*NT + t0
    const int u0 = uslab * CTA_N;
    const int mwarp = wid & 1;        // 2 warps along M
    const int nwarp = wid >> 1;       // 4 warps along N

    // 1024B-aligned SMEM base (SW128 swizzle requires it)
    const uint32_t sb = sptr(dynsmem);
    const uint32_t tb = (sb + 1023u) & ~1023u;

    for (int i = tid; i < CTA_N; i += 256) {
        int qidx = (int)(arow0 >> 10) * NU + u0 + i;   // b = arow0/1024
        s_qp[i] = g_qproj[qidx] + g_qproj[NB * NU + qidx]
                + g_qproj[2 * NB * NU + qidx] + g_qproj[3 * NB * NU + qidx];
        s_V[i]  = Vv[u0 + i];
    }

    const __half* asrc0 = g_valh + arow0 * ND;
    const __half* bsrc0 = g_w1h + (size_t)u0 * ND;

    // ---- stage loader: A 128x64 fp16 + B 256x64 fp16, SW128 swizzled ----
    auto load_stage = [&](int kt, int st) {
        uint32_t ab = tb + st * STAGE_BYTES;
        uint32_t bb = ab + CTA_M * KC * 2;
        const __half* asrc = asrc0 + (size_t)kt * KC;
        #pragma unroll
        for (int i = 0; i < 4; i++) {           // 1024 chunks of 16B
            int c = tid + i * 256;
            int r = c >> 3, k8 = c & 7;
            cpasync16(ab + SW128((uint32_t)(r * 128 + k8 * 16)),
                      asrc + (size_t)r * ND + k8 * 8);
        }
        const __half* bsrc = bsrc0 + (size_t)kt * KC;
        #pragma unroll
        for (int i = 0; i < 8; i++) {           // 2048 chunks of 16B
            int c = tid + i * 256;
            int r = c >> 3, k8 = c & 7;
            cpasync16(bb + SW128((uint32_t)(r * 128 + k8 * 16)),
                      bsrc + (size_t)r * ND + k8 * 8);
        }
        CP_COMMIT();
    };

    float acc[4][8][4];
    #pragma unroll
    for (int mt = 0; mt < 4; mt++)
        #pragma unroll
        for (int nt = 0; nt < 8; nt++)
            #pragma unroll
            for (int i = 0; i < 4; i++) acc[mt][nt][i] = 0.f;

    load_stage(0, 0);
    load_stage(1, 1);
    load_stage(2, 2);

    for (int kt = 0; kt < NKT; kt++) {
        CP_WAIT2();              // oldest (stage kt) complete for this thread
        __syncthreads();         // whole tile visible; stage (kt+3)%4 drained
        if (kt + 3 < NKT) load_stage(kt + 3, (kt + 3) & 3);
        else              CP_COMMIT();       // keep group accounting aligned

        uint32_t ab = tb + (kt & 3) * STAGE_BYTES;
        uint32_t bb = ab + CTA_M * KC * 2;

        #pragma unroll
        for (int ks = 0; ks < 4; ks++) {        // 4 k16-steps per chunk
            uint32_t a_r[4][4], b_r[4][4];
            #pragma unroll
            for (int mt = 0; mt < 4; mt++) {
                int r    = mwarp * 64 + mt * 16 + (lane & 15);
                int kcol = ks * 16 + ((lane >> 4) << 3);
                ldsm4(a_r[mt], ab + SW128((uint32_t)(r * 128 + kcol * 2)));
            }
            #pragma unroll
            for (int j = 0; j < 4; j++) {       // each covers 2 n-tiles (n16)
                int r    = nwarp * 64 + j * 16 + (lane & 7) + ((lane >> 4) << 3);
                int kcol = ks * 16 + ((lane >> 3) & 1) * 8;
                ldsm4(b_r[j], bb + SW128((uint32_t)(r * 128 + kcol * 2)));
            }
            #pragma unroll
            for (int mt = 0; mt < 4; mt++)
                #pragma unroll
                for (int nt = 0; nt < 8; nt++)
                    mma16816(acc[mt][nt], a_r[mt], b_r[nt >> 1] + (nt & 1) * 2);
        }
    }

    // ---- epilogue: per-row partial score = sum_u tanh(c + qp[u]) * V[u] ----
    #pragma unroll
    for (int mt = 0; mt < 4; mt++) {
        float rs0 = 0.f, rs1 = 0.f;   // rows (base) and (base+8)
        #pragma unroll
        for (int nt = 0; nt < 8; nt++) {
            int col = nwarp * 64 + nt * 8 + (lane & 3) * 2;
            rs0 += fast_tanh(acc[mt][nt][0] + s_qp[col])     * s_V[col];
            rs0 += fast_tanh(acc[mt][nt][1] + s_qp[col + 1]) * s_V[col + 1];
            rs1 += fast_tanh(acc[mt][nt][2] + s_qp[col])     * s_V[col];
            rs1 += fast_tanh(acc[mt][nt][3] + s_qp[col + 1]) * s_V[col + 1];
        }
        rs0 += __shfl_xor_sync(0xFFFFFFFF, rs0, 1);
        rs0 += __shfl_xor_sync(0xFFFFFFFF, rs0, 2);
        rs1 += __shfl_xor_sync(0xFFFFFFFF, rs1, 1);
        rs1 += __shfl_xor_sync(0xFFFFFFFF, rs1, 2);
        if ((lane & 3) == 0) {
            int row = mwarp * 64 + mt * 16 + (lane >> 2);
            s_red[row][nwarp]     = rs0;
            s_red[row + 8][nwarp] = rs1;
        }
    }
    __syncthreads();
    if (tid < CTA_M) {
        float s = s_red[tid][0] + s_red[tid][1] + s_red[tid][2] + s_red[tid][3];
        g_pscore[(size_t)uslab * NB * NT + arow0 + tid] = s;
    }
}

// ---------------------------------------------------------------------------
// Kernel 3: fused softmax + context. grid (NB, ND/256), 256 threads.
// Softmax recomputed per block (tiny). Context: warp w owns t-range
// [w*128,(w+1)*128); each lane owns 4 half2 columns (MLP=8 with 2-t unroll);
// cross-warp reduction through SMEM.
// ---------------------------------------------------------------------------
__global__ void __launch_bounds__(256) softmax_context_kernel(
    float* __restrict__ out_w, float* __restrict__ out_ctx) {
    __shared__ float sw_[NT];
    __shared__ float red[256];
    __shared__ float2 s_part[8][128];
    const int b = blockIdx.x;
    const int tid = threadIdx.x;
    const int wid = tid >> 5;
    const int lane = tid & 31;

    float s[4];
    float m = -3.0e38f;
    #pragma unroll
    for (int j = 0; j < 4; j++) {
        int t = j * 256 + tid;
        float v = 0.f;
        #pragma unroll
        for (int k = 0; k < NSLAB; k++)
            v += g_pscore[k * NB * NT + b * NT + t];
        s[j] = v;
        m = fmaxf(m, v);
    }
    red[tid] = m;
    __syncthreads();
    #pragma unroll
    for (int k = 128; k > 0; k >>= 1) {
        if (tid < k) red[tid] = fmaxf(red[tid], red[tid + k]);
        __syncthreads();
    }
    float mx = red[0];
    __syncthreads();
    float sum = 0.f;
    #pragma unroll
    for (int j = 0; j < 4; j++) { s[j] = __expf(s[j] - mx); sum += s[j]; }
    red[tid] = sum;
    __syncthreads();
    #pragma unroll
    for (int k = 128; k > 0; k >>= 1) {
        if (tid < k) red[tid] += red[tid + k];
        __syncthreads();
    }
    float inv = 1.0f / red[0];
    #pragma unroll
    for (int j = 0; j < 4; j++) {
        int t = j * 256 + tid;
        float w = s[j] * inv;
        sw_[t] = w;
        if (blockIdx.y == 0) out_w[b * NT + t] = w;
    }
    __syncthreads();

    // context: 256-d slice at blockIdx.y*256; half2 column index = lane + c*32
    const __half2* vp = (const __half2*)(g_valh + (size_t)b * NT * ND
                                         + blockIdx.y * 256);
    constexpr int S2 = ND / 2;   // half2 stride per t
    float2 acc[4];
    #pragma unroll
    for (int c = 0; c < 4; c++) acc[c] = make_float2(0.f, 0.f);

    const int tbeg = wid * 128;
    #pragma unroll 2
    for (int tt = 0; tt < 128; tt++) {
        int t = tbeg + tt;
        float w = sw_[t];
        #pragma unroll
        for (int c = 0; c < 4; c++) {
            float2 v = __half22float2(vp[(size_t)t * S2 + lane + c * 32]);
            acc[c].x = fmaf(w, v.x, acc[c].x);
            acc[c].y = fmaf(w, v.y, acc[c].y);
        }
    }
    #pragma unroll
    for (int c = 0; c < 4; c++) s_part[wid][lane + c * 32] = acc[c];
    __syncthreads();

    if (tid < 128) {
        float2 r = make_float2(0.f, 0.f);
        #pragma unroll
        for (int w8 = 0; w8 < 8; w8++) {
            r.x += s_part[w8][tid].x;
            r.y += s_part[w8][tid].y;
        }
        *(float2*)(out_ctx + b * ND + blockIdx.y * 256 + tid * 2) = r;
    }
}

// ---------------------------------------------------------------------------
// Launch
// ---------------------------------------------------------------------------
extern "C" void kernel_launch(void* const* d_in, const int* in_sizes, int n_in,
                              void* d_out, int out_size) {
    (void)in_sizes; (void)n_in; (void)out_size;
    const float* query  = (const float*)d_in[0];
    const float* values = (const float*)d_in[1];
    const float* W1     = (const float*)d_in[2];
    const float* b1     = (const float*)d_in[3];
    const float* W2     = (const float*)d_in[4];
    const float* b2     = (const float*)d_in[5];
    const float* Vv     = (const float*)d_in[6];
    // d_in[7] = bv: constant pre-softmax shift -> cancels under softmax.

    float* out     = (float*)d_out;
    float* out_ctx = out;              // context_vector (B, D)
    float* out_w   = out + NB * ND;    // attention_weights (B, T, 1)

    cudaFuncSetAttribute(gemm_score_kernel,
                         cudaFuncAttributeMaxDynamicSharedMemorySize, SMEM_DYN);

    fused_prep_kernel<<<PREP_BLOCKS, 256>>>(values, W1, query, W2, b1, b2);
    gemm_score_kernel<<<dim3(NSLAB, (NB * NT) / CTA_M), 256, SMEM_DYN>>>(Vv);
    softmax_context_kernel<<<dim3(NB, ND / 256), 256>>>(out_w, out_ctx);
}

// round 15
// speedup vs baseline: 1.6516x; 1.0614x over previous
#include <cuda_runtime.h>
#include <cuda_fp16.h>
#include <stdint.h>

// ---------------------------------------------------------------------------
// Problem constants
// ---------------------------------------------------------------------------
constexpr int NB = 32;
constexpr int NT = 1024;
constexpr int ND = 2048;
constexpr int NU = 1024;

// GEMM tiling: C[32768,1024] = A[32768,2048] * B[2048,1024] (B = W1)
constexpr int CTA_M = 128;
constexpr int CTA_N = 128;          // smaller tile -> 2 CTAs/SM
constexpr int KC    = 64;           // k-chunk (64 fp16 = 128B row -> SW128)
constexpr int NKT   = ND / KC;      // 32
constexpr int NSLAB = NU / CTA_N;   // 8 partial-score slabs
constexpr int NSTG  = 3;            // cp.async pipeline stages
constexpr int NQCH  = 4;            // qproj d-split chunks

constexpr int STAGE_BYTES = CTA_M * KC * 2 + CTA_N * KC * 2;  // 16K + 16K = 32K
constexpr int SMEM_DYN    = 1024 + NSTG * STAGE_BYTES;        // 99328

#define SW128(o) ((o) ^ (((o) >> 3) & 0x70))

// ---------------------------------------------------------------------------
// Device scratch (__device__ globals: allocation-free rule)
// ---------------------------------------------------------------------------
__device__ __align__(256) __half g_valh[(size_t)NB * NT * ND];  // values in fp16
__device__ __align__(256) __half g_w1h[(size_t)NU * ND];        // W1^T fp16 [U][D]
__device__ float g_qproj[NQCH * NB * NU];                       // partial qproj
__device__ float g_pscore[NSLAB * NB * NT];                     // partial scores

// ---------------------------------------------------------------------------
// PTX helpers (baseline sm_80 features only: safe for compute_103 target)
// ---------------------------------------------------------------------------
__device__ __forceinline__ uint32_t sptr(const void* p) {
    return (uint32_t)__cvta_generic_to_shared(p);
}

__device__ __forceinline__ void cpasync16(uint32_t dst, const void* src) {
    asm volatile("cp.async.cg.shared.global [%0], [%1], 16;" :: "r"(dst), "l"(src));
}
#define CP_COMMIT() asm volatile("cp.async.commit_group;" ::: "memory")
#define CP_WAIT1()  asm volatile("cp.async.wait_group 1;" ::: "memory")

__device__ __forceinline__ void ldsm4(uint32_t* r, uint32_t addr) {
    asm volatile("ldmatrix.sync.aligned.m8n8.x4.shared.b16 {%0,%1,%2,%3}, [%4];"
                 : "=r"(r[0]), "=r"(r[1]), "=r"(r[2]), "=r"(r[3]) : "r"(addr));
}

__device__ __forceinline__ void mma16816(float* d, const uint32_t* a,
                                         const uint32_t* b) {
    asm volatile(
        "mma.sync.aligned.m16n8k16.row.col.f32.f16.f16.f32 "
        "{%0,%1,%2,%3}, {%4,%5,%6,%7}, {%8,%9}, {%0,%1,%2,%3};"
        : "+f"(d[0]), "+f"(d[1]), "+f"(d[2]), "+f"(d[3])
        : "r"(a[0]), "r"(a[1]), "r"(a[2]), "r"(a[3]), "r"(b[0]), "r"(b[1]));
}

// fast accurate tanh: 1 - 2/(exp(2x)+1); saturates correctly at +-inf
__device__ __forceinline__ float fast_tanh(float x) {
    float e = __expf(2.0f * x);
    return 1.0f - __fdividef(2.0f, e + 1.0f);
}

__device__ __forceinline__ uint32_t pack_h2(float a, float b) {
    __half2 h = __floats2half2_rn(a, b);
    return *(uint32_t*)&h;
}

// ---------------------------------------------------------------------------
// Kernel 1 (fused prep): qproj(d-split) | W1 transpose | values->fp16
// ---------------------------------------------------------------------------
constexpr int QP_BLOCKS = NQCH * NB * (NU / 256);     // 512
constexpr int PW_BLOCKS = (NU / 32) * (ND / 32);      // 2048
// convert: 4 float4 per thread at block stride 256 (coalesced, MLP=4)
constexpr int PV_F4     = (int)(((size_t)NB * NT * ND) / 4);   // 16M float4
constexpr int PV_BLOCKS = PV_F4 / (256 * 4);                   // 16384
constexpr int PREP_BLOCKS = QP_BLOCKS + PW_BLOCKS + PV_BLOCKS;

__global__ void __launch_bounds__(256) fused_prep_kernel(
    const float* __restrict__ values, const float* __restrict__ W1,
    const float* __restrict__ query,  const float* __restrict__ W2,
    const float* __restrict__ b1,     const float* __restrict__ b2) {
    int bi = blockIdx.x;
    int tid = threadIdx.x;

    if (bi < QP_BLOCKS) {
        // partial qproj over d-chunk: chunk = bi%4, (b,u-quarter) = bi/4
        int chunk = bi & (NQCH - 1);
        int rest  = bi >> 2;
        int b = rest >> 2;
        int u = (rest & 3) * 256 + tid;
        int d0 = chunk * (ND / NQCH);                 // 512-wide chunk
        const float* q = query + (size_t)b * ND + d0;
        const float* w = W2 + (size_t)d0 * NU + u;
        float a0 = 0.f, a1 = 0.f, a2 = 0.f, a3 = 0.f;
        #pragma unroll 2
        for (int d = 0; d < ND / NQCH; d += 4) {
            a0 = fmaf(q[d + 0], w[(size_t)(d + 0) * NU], a0);
            a1 = fmaf(q[d + 1], w[(size_t)(d + 1) * NU], a1);
            a2 = fmaf(q[d + 2], w[(size_t)(d + 2) * NU], a2);
            a3 = fmaf(q[d + 3], w[(size_t)(d + 3) * NU], a3);
        }
        float r = (a0 + a1) + (a2 + a3);
        if (chunk == 0) r += b1[u] + b2[u];
        g_qproj[chunk * NB * NU + b * NU + u] = r;
        return;
    }
    bi -= QP_BLOCKS;
    if (bi < PW_BLOCKS) {
        // W1 [D][U] fp32 -> W1^T [U][D] fp16, 32x32 tiles
        __shared__ __half tile[32][33];
        int u0 = (bi & 31) * 32;          // NU/32 = 32
        int d0 = (bi >> 5) * 32;
        int c = tid & 31;
        int r0 = tid >> 5;
        #pragma unroll
        for (int rr = 0; rr < 4; rr++) {
            int r = r0 + rr * 8;
            tile[r][c] = __float2half(W1[(size_t)(d0 + r) * NU + u0 + c]);
        }
        __syncthreads();
        #pragma unroll
        for (int rr = 0; rr < 4; rr++) {
            int r = r0 + rr * 8;
            g_w1h[(size_t)(u0 + r) * ND + d0 + c] = tile[c][r];
        }
        return;
    }
    bi -= PW_BLOCKS;
    // values fp32 -> fp16: 4 float4 per thread, BLOCK-STRIDED (coalesced MLP=4)
    size_t f4base = (size_t)bi * (256 * 4) + tid;
    const float4* src = (const float4*)values;
    float4 x0 = src[f4base];
    float4 x1 = src[f4base + 256];
    float4 x2 = src[f4base + 512];
    float4 x3 = src[f4base + 768];
    uint2* dst = (uint2*)g_valh;
    dst[f4base]       = make_uint2(pack_h2(x0.x, x0.y), pack_h2(x0.z, x0.w));
    dst[f4base + 256] = make_uint2(pack_h2(x1.x, x1.y), pack_h2(x1.z, x1.w));
    dst[f4base + 512] = make_uint2(pack_h2(x2.x, x2.y), pack_h2(x2.z, x2.w));
    dst[f4base + 768] = make_uint2(pack_h2(x3.x, x3.y), pack_h2(x3.z, x3.w));
}

// ---------------------------------------------------------------------------
// Kernel 2: fused fp16 GEMM (mma.sync, 3-stage cp.async, 2 CTAs/SM)
// grid (NSLAB=8, 256 m-tiles), 256 threads, warp tile 64x32
// ---------------------------------------------------------------------------
__global__ void __launch_bounds__(256, 2)
gemm_score_kernel(const float* __restrict__ Vv) {
    extern __shared__ char dynsmem[];
    __shared__ float s_qp[CTA_N];
    __shared__ float s_V[CTA_N];
    __shared__ float s_red[CTA_M][4];

    const int tid  = threadIdx.x;
    const int wid  = tid >> 5;
    const int lane = tid & 31;
    const int uslab = blockIdx.x;
    const int mtile = blockIdx.y;
    const size_t arow0 = (size_t)mtile * CTA_M;   // global row = b*NT + t0
    const int u0 = uslab * CTA_N;
    const int mwarp = wid & 1;        // 2 warps along M (64 rows each)
    const int nwarp = wid >> 1;       // 4 warps along N (32 cols each)

    // 1024B-aligned SMEM base (SW128 swizzle requires it)
    const uint32_t sb = sptr(dynsmem);
    const uint32_t tb = (sb + 1023u) & ~1023u;

    for (int i = tid; i < CTA_N; i += 256) {
        int qidx = (int)(arow0 >> 10) * NU + u0 + i;   // b = arow0/1024
        s_qp[i] = g_qproj[qidx] + g_qproj[NB * NU + qidx]
                + g_qproj[2 * NB * NU + qidx] + g_qproj[3 * NB * NU + qidx];
        s_V[i]  = Vv[u0 + i];
    }

    const __half* asrc0 = g_valh + arow0 * ND;
    const __half* bsrc0 = g_w1h + (size_t)u0 * ND;

    // ---- stage loader: A 128x64 + B 128x64 fp16, SW128 swizzled ----
    auto load_stage = [&](int kt, int st) {
        uint32_t ab = tb + st * STAGE_BYTES;
        uint32_t bb = ab + CTA_M * KC * 2;
        const __half* asrc = asrc0 + (size_t)kt * KC;
        #pragma unroll
        for (int i = 0; i < 4; i++) {           // 1024 chunks of 16B
            int c = tid + i * 256;
            int r = c >> 3, k8 = c & 7;
            cpasync16(ab + SW128((uint32_t)(r * 128 + k8 * 16)),
                      asrc + (size_t)r * ND + k8 * 8);
        }
        const __half* bsrc = bsrc0 + (size_t)kt * KC;
        #pragma unroll
        for (int i = 0; i < 4; i++) {           // 1024 chunks of 16B
            int c = tid + i * 256;
            int r = c >> 3, k8 = c & 7;
            cpasync16(bb + SW128((uint32_t)(r * 128 + k8 * 16)),
                      bsrc + (size_t)r * ND + k8 * 8);
        }
        CP_COMMIT();
    };

    float acc[4][4][4];
    #pragma unroll
    for (int mt = 0; mt < 4; mt++)
        #pragma unroll
        for (int nt = 0; nt < 4; nt++)
            #pragma unroll
            for (int i = 0; i < 4; i++) acc[mt][nt][i] = 0.f;

    load_stage(0, 0);
    load_stage(1, 1);

    int scur = 0, snext = 2;
    for (int kt = 0; kt < NKT; kt++) {
        CP_WAIT1();              // stage kt complete (<=1 group pending)
        __syncthreads();         // stage snext's old readers all past barrier
        if (kt + 2 < NKT) load_stage(kt + 2, snext);
        else              CP_COMMIT();       // keep group accounting aligned

        uint32_t ab = tb + scur * STAGE_BYTES;
        uint32_t bb = ab + CTA_M * KC * 2;

        #pragma unroll
        for (int ks = 0; ks < 4; ks++) {        // 4 k16-steps per chunk
            uint32_t a_r[4][4], b_r[2][4];
            #pragma unroll
            for (int mt = 0; mt < 4; mt++) {
                int r    = mwarp * 64 + mt * 16 + (lane & 15);
                int kcol = ks * 16 + ((lane >> 4) << 3);
                ldsm4(a_r[mt], ab + SW128((uint32_t)(r * 128 + kcol * 2)));
            }
            #pragma unroll
            for (int j = 0; j < 2; j++) {       // each covers 2 n8-tiles
                int r    = nwarp * 32 + j * 16 + (lane & 7) + ((lane >> 4) << 3);
                int kcol = ks * 16 + ((lane >> 3) & 1) * 8;
                ldsm4(b_r[j], bb + SW128((uint32_t)(r * 128 + kcol * 2)));
            }
            #pragma unroll
            for (int mt = 0; mt < 4; mt++)
                #pragma unroll
                for (int nt = 0; nt < 4; nt++)
                    mma16816(acc[mt][nt], a_r[mt], b_r[nt >> 1] + (nt & 1) * 2);
        }
        scur  = (scur  == NSTG - 1) ? 0 : scur + 1;
        snext = (snext == NSTG - 1) ? 0 : snext + 1;
    }

    // ---- epilogue: per-row partial score = sum_u tanh(c + qp[u]) * V[u] ----
    #pragma unroll
    for (int mt = 0; mt < 4; mt++) {
        float rs0 = 0.f, rs1 = 0.f;   // rows (base) and (base+8)
        #pragma unroll
        for (int nt = 0; nt < 4; nt++) {
            int col = nwarp * 32 + nt * 8 + (lane & 3) * 2;
            rs0 += fast_tanh(acc[mt][nt][0] + s_qp[col])     * s_V[col];
            rs0 += fast_tanh(acc[mt][nt][1] + s_qp[col + 1]) * s_V[col + 1];
            rs1 += fast_tanh(acc[mt][nt][2] + s_qp[col])     * s_V[col];
            rs1 += fast_tanh(acc[mt][nt][3] + s_qp[col + 1]) * s_V[col + 1];
        }
        rs0 += __shfl_xor_sync(0xFFFFFFFF, rs0, 1);
        rs0 += __shfl_xor_sync(0xFFFFFFFF, rs0, 2);
        rs1 += __shfl_xor_sync(0xFFFFFFFF, rs1, 1);
        rs1 += __shfl_xor_sync(0xFFFFFFFF, rs1, 2);
        if ((lane & 3) == 0) {
            int row = mwarp * 64 + mt * 16 + (lane >> 2);
            s_red[row][nwarp]     = rs0;
            s_red[row + 8][nwarp] = rs1;
        }
    }
    __syncthreads();
    if (tid < CTA_M) {
        float s = s_red[tid][0] + s_red[tid][1] + s_red[tid][2] + s_red[tid][3];
        g_pscore[(size_t)uslab * NB * NT + arow0 + tid] = s;
    }
}

// ---------------------------------------------------------------------------
// Kernel 3: fused softmax + context. grid (NB, ND/256), 256 threads.
// Softmax recomputed per block (tiny). Context: warp w owns t-range
// [w*128,(w+1)*128); each lane owns 4 half2 columns; SMEM cross-warp reduce.
// ---------------------------------------------------------------------------
__global__ void __launch_bounds__(256) softmax_context_kernel(
    float* __restrict__ out_w, float* __restrict__ out_ctx) {
    __shared__ float sw_[NT];
    __shared__ float red[256];
    __shared__ float2 s_part[8][128];
    const int b = blockIdx.x;
    const int tid = threadIdx.x;
    const int wid = tid >> 5;
    const int lane = tid & 31;

    float s[4];
    float m = -3.0e38f;
    #pragma unroll
    for (int j = 0; j < 4; j++) {
        int t = j * 256 + tid;
        float v = 0.f;
        #pragma unroll
        for (int k = 0; k < NSLAB; k++)
            v += g_pscore[k * NB * NT + b * NT + t];
        s[j] = v;
        m = fmaxf(m, v);
    }
    red[tid] = m;
    __syncthreads();
    #pragma unroll
    for (int k = 128; k > 0; k >>= 1) {
        if (tid < k) red[tid] = fmaxf(red[tid], red[tid + k]);
        __syncthreads();
    }
    float mx = red[0];
    __syncthreads();
    float sum = 0.f;
    #pragma unroll
    for (int j = 0; j < 4; j++) { s[j] = __expf(s[j] - mx); sum += s[j]; }
    red[tid] = sum;
    __syncthreads();
    #pragma unroll
    for (int k = 128; k > 0; k >>= 1) {
        if (tid < k) red[tid] += red[tid + k];
        __syncthreads();
    }
    float inv = 1.0f / red[0];
    #pragma unroll
    for (int j = 0; j < 4; j++) {
        int t = j * 256 + tid;
        float w = s[j] * inv;
        sw_[t] = w;
        if (blockIdx.y == 0) out_w[b * NT + t] = w;
    }
    __syncthreads();

    // context: 256-d slice at blockIdx.y*256; half2 column index = lane + c*32
    const __half2* vp = (const __half2*)(g_valh + (size_t)b * NT * ND
                                         + blockIdx.y * 256);
    constexpr int S2 = ND / 2;   // half2 stride per t
    float2 acc[4];
    #pragma unroll
    for (int c = 0; c < 4; c++) acc[c] = make_float2(0.f, 0.f);

    const int tbeg = wid * 128;
    #pragma unroll 2
    for (int tt = 0; tt < 128; tt++) {
        int t = tbeg + tt;
        float w = sw_[t];
        #pragma unroll
        for (int c = 0; c < 4; c++) {
            float2 v = __half22float2(vp[(size_t)t * S2 + lane + c * 32]);
            acc[c].x = fmaf(w, v.x, acc[c].x);
            acc[c].y = fmaf(w, v.y, acc[c].y);
        }
    }
    #pragma unroll
    for (int c = 0; c < 4; c++) s_part[wid][lane + c * 32] = acc[c];
    __syncthreads();

    if (tid < 128) {
        float2 r = make_float2(0.f, 0.f);
        #pragma unroll
        for (int w8 = 0; w8 < 8; w8++) {
            r.x += s_part[w8][tid].x;
            r.y += s_part[w8][tid].y;
        }
        *(float2*)(out_ctx + b * ND + blockIdx.y * 256 + tid * 2) = r;
    }
}

// ---------------------------------------------------------------------------
// Launch
// ---------------------------------------------------------------------------
extern "C" void kernel_launch(void* const* d_in, const int* in_sizes, int n_in,
                              void* d_out, int out_size) {
    (void)in_sizes; (void)n_in; (void)out_size;
    const float* query  = (const float*)d_in[0];
    const float* values = (const float*)d_in[1];
    const float* W1     = (const float*)d_in[2];
    const float* b1     = (const float*)d_in[3];
    const float* W2     = (const float*)d_in[4];
    const float* b2     = (const float*)d_in[5];
    const float* Vv     = (const float*)d_in[6];
    // d_in[7] = bv: constant pre-softmax shift -> cancels under softmax.

    float* out     = (float*)d_out;
    float* out_ctx = out;              // context_vector (B, D)
    float* out_w   = out + NB * ND;    // attention_weights (B, T, 1)

    cudaFuncSetAttribute(gemm_score_kernel,
                         cudaFuncAttributeMaxDynamicSharedMemorySize, SMEM_DYN);

    fused_prep_kernel<<<PREP_BLOCKS, 256>>>(values, W1, query, W2, b1, b2);
    gemm_score_kernel<<<dim3(NSLAB, (NB * NT) / CTA_M), 256, SMEM_DYN>>>(Vv);
    softmax_context_kernel<<<dim3(NB, ND / 256), 256>>>(out_w, out_ctx);
}